// round 1
// baseline (speedup 1.0000x reference)
#include <cuda_runtime.h>
#include <math.h>

// Problem constants (T=5, B=4, M=4096, C=128, G=1024, H=4, K=16)
#define T_FR   5
#define NPTS   16384
#define CDIM   128
#define GDIM   1024
#define HHEADS 4
#define BATCH  4
#define MP     4096
#define KNB    16

// ---------------- scratch (static __device__ — no allocations) ----------------
__device__ float g_H1[81920 * 128];          // leaky(seq@W1+b1)      ~42 MB
__device__ float g_XLR[5 * 16384 * 512];     // [0..3]=past@Wr, [4]=last@Wl  ~168 MB
__device__ float g_gf[5 * 4 * 1024];         // global_fea means
__device__ float g_attn[16];                 // attn[b][t]
__device__ int   g_nbr[4 * 16384 * 16];      // knn indices (global row ids)
__device__ float g_res[4 * 16384 * 128];     // per-frame GAT outputs ~34 MB

// ---------------- small init ----------------
__global__ void zero_gf_kernel() {
    int i = blockIdx.x * 256 + threadIdx.x;
    if (i < 5 * 4 * 1024) g_gf[i] = 0.f;
}

// ---------------- generic fp32 GEMM, K=128, 64x64 tile, 4x4 micro ----------------
__global__ __launch_bounds__(256) void gemm_k128(
    const float* __restrict__ A, const float* __restrict__ B,
    const float* __restrict__ bias, float* __restrict__ C,
    int Ncols, int leaky)
{
    __shared__ float As[64][68];   // [k][row], padded (68*4B = 272B, 16B-aligned rows)
    __shared__ float Bs[64][68];   // [k][col]
    const int tid = threadIdx.x;
    const int tx = tid & 15, ty = tid >> 4;
    const size_t row0 = (size_t)blockIdx.x * 64;
    const int col0 = blockIdx.y * 64;

    float acc[4][4];
#pragma unroll
    for (int a = 0; a < 4; a++)
#pragma unroll
        for (int bb = 0; bb < 4; bb++) acc[a][bb] = 0.f;

    for (int kc = 0; kc < 2; kc++) {
        const int ks = kc * 64;
#pragma unroll
        for (int it = 0; it < 4; it++) {          // A tile 64 rows x 64 k (transposed store)
            int idx = tid + it * 256;
            int rr = idx >> 4; int kq = (idx & 15) * 4;
            float4 v = *(const float4*)(A + (row0 + rr) * 128 + ks + kq);
            As[kq + 0][rr] = v.x; As[kq + 1][rr] = v.y;
            As[kq + 2][rr] = v.z; As[kq + 3][rr] = v.w;
        }
#pragma unroll
        for (int it = 0; it < 4; it++) {          // B tile 64 k x 64 cols
            int idx = tid + it * 256;
            int kk = idx >> 4; int c4 = (idx & 15) * 4;
            *(float4*)&Bs[kk][c4] = *(const float4*)(B + (size_t)(ks + kk) * Ncols + col0 + c4);
        }
        __syncthreads();
#pragma unroll 16
        for (int k = 0; k < 64; k++) {
            float av[4], bv[4];
#pragma unroll
            for (int j = 0; j < 4; j++) av[j] = As[k][ty + 16 * j];
#pragma unroll
            for (int j = 0; j < 4; j++) bv[j] = Bs[k][tx + 16 * j];
#pragma unroll
            for (int a = 0; a < 4; a++)
#pragma unroll
                for (int bb = 0; bb < 4; bb++) acc[a][bb] += av[a] * bv[bb];
        }
        __syncthreads();
    }
#pragma unroll
    for (int a = 0; a < 4; a++) {
        int r = ty + 16 * a;
#pragma unroll
        for (int bb = 0; bb < 4; bb++) {
            int c = tx + 16 * bb;
            float v = acc[a][bb];
            if (bias) v += bias[col0 + c];
            if (leaky && v < 0.f) v *= 0.2f;
            C[(row0 + r) * Ncols + col0 + c] = v;
        }
    }
}

// ---------------- GEMM2 fused with leaky + column-mean reduce into g_gf ----------------
__global__ __launch_bounds__(256) void gemm2_reduce_kernel(
    const float* __restrict__ A, const float* __restrict__ B,
    const float* __restrict__ bias)
{
    __shared__ float As[64][68];
    __shared__ float Bs[64][68];
    __shared__ float sred[64];
    const int Ncols = GDIM;
    const int tid = threadIdx.x;
    const int tx = tid & 15, ty = tid >> 4;
    const size_t row0 = (size_t)blockIdx.x * 64;
    const int col0 = blockIdx.y * 64;

    float acc[4][4];
#pragma unroll
    for (int a = 0; a < 4; a++)
#pragma unroll
        for (int bb = 0; bb < 4; bb++) acc[a][bb] = 0.f;

    for (int kc = 0; kc < 2; kc++) {
        const int ks = kc * 64;
#pragma unroll
        for (int it = 0; it < 4; it++) {
            int idx = tid + it * 256;
            int rr = idx >> 4; int kq = (idx & 15) * 4;
            float4 v = *(const float4*)(A + (row0 + rr) * 128 + ks + kq);
            As[kq + 0][rr] = v.x; As[kq + 1][rr] = v.y;
            As[kq + 2][rr] = v.z; As[kq + 3][rr] = v.w;
        }
#pragma unroll
        for (int it = 0; it < 4; it++) {
            int idx = tid + it * 256;
            int kk = idx >> 4; int c4 = (idx & 15) * 4;
            *(float4*)&Bs[kk][c4] = *(const float4*)(B + (size_t)(ks + kk) * Ncols + col0 + c4);
        }
        __syncthreads();
#pragma unroll 16
        for (int k = 0; k < 64; k++) {
            float av[4], bv[4];
#pragma unroll
            for (int j = 0; j < 4; j++) av[j] = As[k][ty + 16 * j];
#pragma unroll
            for (int j = 0; j < 4; j++) bv[j] = Bs[k][tx + 16 * j];
#pragma unroll
            for (int a = 0; a < 4; a++)
#pragma unroll
                for (int bb = 0; bb < 4; bb++) acc[a][bb] += av[a] * bv[bb];
        }
        __syncthreads();
    }
    if (tid < 64) sred[tid] = 0.f;
    __syncthreads();
#pragma unroll
    for (int bb = 0; bb < 4; bb++) {
        int c = tx + 16 * bb;
        float bv = bias[col0 + c];
        float s = 0.f;
#pragma unroll
        for (int a = 0; a < 4; a++) {
            float v = acc[a][bb] + bv;
            if (v < 0.f) v *= 0.2f;
            s += v;
        }
        atomicAdd(&sred[c], s);
    }
    __syncthreads();
    if (tid < 64) {
        int t = (int)(row0 >> 14);          // 16384 rows per frame
        int b = (int)((row0 >> 12) & 3);    // 4096 rows per batch
        atomicAdd(&g_gf[(t * 4 + b) * GDIM + col0 + tid], sred[tid] * (1.f / (float)MP));
    }
}

// ---------------- temporal attention weights (tiny) ----------------
__global__ void attn_kernel() {
    __shared__ float sc[16];
    const int tid = threadIdx.x;            // 512
    const int w = tid >> 5, lane = tid & 31;
    const int b = w >> 2, t = w & 3;
    float acc = 0.f;
    for (int g = lane; g < GDIM; g += 32)
        acc += g_gf[(4 * 4 + b) * GDIM + g] * g_gf[(t * 4 + b) * GDIM + g];
#pragma unroll
    for (int o = 16; o; o >>= 1) acc += __shfl_xor_sync(0xffffffffu, acc, o);
    if (lane == 0) sc[b * 4 + t] = acc * (1.f / 32.f);   // /sqrt(1024)
    __syncthreads();
    if (tid < 4) {
        int bb = tid;
        float m = sc[bb * 4];
        for (int i = 1; i < 4; i++) m = fmaxf(m, sc[bb * 4 + i]);
        float e[4], s = 0.f;
        for (int i = 0; i < 4; i++) { e[i] = expf(sc[bb * 4 + i] - m); s += e[i]; }
        for (int i = 0; i < 4; i++) g_attn[bb * 4 + i] = e[i] / s;
    }
}

// ---------------- fused KNN: distance GEMM tile + top-16 selection ----------------
// block = (query-tile of 32, batch, frame). Never materializes D.
#define KNN_SMEM_FLOATS (128*33 + 128*132 + 32*132 + 128 + 32*17 + 32*17)
__global__ __launch_bounds__(256) void knn_kernel(const float* __restrict__ seq) {
    extern __shared__ float sm[];
    float* Ys   = sm;                      // [k][q]  128*33
    float* Xs   = Ys + 128 * 33;           // [k][c]  128*132
    float* Sm   = Xs + 128 * 132;          // [q][c]  32*132
    float* xn   = Sm + 32 * 132;           // 128
    float* topd = xn + 128;                // 32*17 (padded stride 17)
    int*   topi = (int*)(topd + 32 * 17);  // 32*17

    const int tid = threadIdx.x;
    const int qt = blockIdx.x, b = blockIdx.y, fr = blockIdx.z;
    const float* Yb = seq + (size_t)4 * NPTS * CDIM + (size_t)(b * MP + qt * 32) * CDIM;
    const float* Xb = seq + (size_t)fr * NPTS * CDIM + (size_t)b * MP * CDIM;

#pragma unroll
    for (int it = 0; it < 4; it++) {       // Y tile 32 x 128 (transposed)
        int idx = tid + it * 256;
        int q = idx >> 5; int kq = (idx & 31) * 4;
        float4 v = *(const float4*)(Yb + (size_t)q * CDIM + kq);
        Ys[(kq + 0) * 33 + q] = v.x; Ys[(kq + 1) * 33 + q] = v.y;
        Ys[(kq + 2) * 33 + q] = v.z; Ys[(kq + 3) * 33 + q] = v.w;
    }
    for (int e = tid; e < 32 * 16; e += 256) {
        int q = e >> 4, j = e & 15;
        topd[q * 17 + j] = 3.0e38f;
        topi[q * 17 + j] = 0;
    }
    const int tx = tid & 31, ty = tid >> 5;

    for (int cc = 0; cc < MP / 128; cc++) {
        __syncthreads();                   // protect Xs/Sm reuse
#pragma unroll
        for (int it = 0; it < 16; it++) {  // X chunk 128 x 128 (transposed)
            int idx = tid + it * 256;
            int c = idx >> 5; int kq = (idx & 31) * 4;
            float4 v = *(const float4*)(Xb + (size_t)(cc * 128 + c) * CDIM + kq);
            Xs[(kq + 0) * 132 + c] = v.x; Xs[(kq + 1) * 132 + c] = v.y;
            Xs[(kq + 2) * 132 + c] = v.z; Xs[(kq + 3) * 132 + c] = v.w;
        }
        __syncthreads();
        if (tid < 128) {                   // candidate norms
            float s = 0.f;
#pragma unroll 8
            for (int k = 0; k < 128; k++) { float x = Xs[k * 132 + tid]; s += x * x; }
            xn[tid] = s;
        }
        __syncthreads();
        float acc[4][4];
#pragma unroll
        for (int a = 0; a < 4; a++)
#pragma unroll
            for (int bb = 0; bb < 4; bb++) acc[a][bb] = 0.f;
#pragma unroll 8
        for (int k = 0; k < 128; k++) {
            float ya[4], xa[4];
#pragma unroll
            for (int j = 0; j < 4; j++) ya[j] = Ys[k * 33 + ty + 8 * j];
#pragma unroll
            for (int j = 0; j < 4; j++) xa[j] = Xs[k * 132 + tx + 32 * j];
#pragma unroll
            for (int a = 0; a < 4; a++)
#pragma unroll
                for (int bb = 0; bb < 4; bb++) acc[a][bb] += ya[a] * xa[bb];
        }
#pragma unroll
        for (int a = 0; a < 4; a++) {
            int q = ty + 8 * a;
#pragma unroll
            for (int bb = 0; bb < 4; bb++) {
                int c = tx + 32 * bb;
                Sm[q * 132 + c] = xn[c] - 2.f * acc[a][bb];   // |x|^2 - 2 y.x (d minus |y|^2)
            }
        }
        __syncthreads();
        if (tid < 32) {                    // per-query top-16 insertion (tie-stable)
            const int q = tid;
            float* td = topd + q * 17;
            int*   ti = topi + q * 17;
            float worst = td[15];
            for (int c = 0; c < 128; c++) {
                float s = Sm[q * 132 + c];
                if (s < worst) {
                    int j = 15;
                    while (j > 0 && td[j - 1] > s) { td[j] = td[j - 1]; ti[j] = ti[j - 1]; j--; }
                    td[j] = s; ti[j] = cc * 128 + c;
                    worst = td[15];
                }
            }
        }
    }
    __syncthreads();
    for (int e = tid; e < 32 * 16; e += 256) {
        int q = e >> 4, j = e & 15;
        int nglob = b * MP + qt * 32 + q;
        g_nbr[((size_t)fr * NPTS + nglob) * KNB + j] = b * MP + topi[q * 17 + j];
    }
}

// ---------------- GATv2 per (query, frame) ----------------
__global__ __launch_bounds__(128) void gat_kernel(const float* __restrict__ att_w) {
    __shared__ float xls[16 * 512];   // gathered lin_l(last) rows
    __shared__ float xrs[512];
    __shared__ float aws[512];
    __shared__ float es[64];
    __shared__ float as_[64];
    __shared__ int   nb[16];

    const int tid = threadIdx.x;      // 128
    const int n = blockIdx.x, fr = blockIdx.y;
    const float* XL = g_XLR + (size_t)4 * NPTS * 512;
    const float* XR = g_XLR + (size_t)fr * NPTS * 512;

    *(float4*)&xrs[tid * 4] = *(const float4*)(XR + (size_t)n * 512 + tid * 4);
    *(float4*)&aws[tid * 4] = *(const float4*)(att_w + tid * 4);
    if (tid < 16) nb[tid] = g_nbr[((size_t)fr * NPTS + n) * KNB + tid];
    __syncthreads();
#pragma unroll
    for (int k = 0; k < 16; k++)
        *(float4*)&xls[k * 512 + tid * 4] = *(const float4*)(XL + (size_t)nb[k] * 512 + tid * 4);
    __syncthreads();

    if (tid < 64) {                   // e[k][h] = att_w[h] . leaky(xlj + xr)
        const int k = tid & 15, h = tid >> 4;
        float acc = 0.f;
#pragma unroll 4
        for (int cc = 0; cc < 128; cc++) {
            int c = (tid + cc) & 127; // stagger -> conflict-free
            float v = xls[k * 512 + h * 128 + c] + xrs[h * 128 + c];
            v = (v < 0.f) ? 0.2f * v : v;
            acc += aws[h * 128 + c] * v;
        }
        es[h * 16 + k] = acc;
    }
    __syncthreads();
    if (tid < 4) {                    // softmax over k per head
        const int h = tid;
        float m = -1e30f;
        for (int k = 0; k < 16; k++) m = fmaxf(m, es[h * 16 + k]);
        float ex[16], s = 0.f;
        for (int k = 0; k < 16; k++) { ex[k] = expf(es[h * 16 + k] - m); s += ex[k]; }
        float inv = 1.f / s;
        for (int k = 0; k < 16; k++) as_[h * 16 + k] = ex[k] * inv;
    }
    __syncthreads();
    {
        float o = 0.f;
#pragma unroll
        for (int h = 0; h < 4; h++) {
            float oh = 0.f;
#pragma unroll
            for (int k = 0; k < 16; k++)
                oh += as_[h * 16 + k] * xls[k * 512 + h * 128 + tid];
            o += oh;
        }
        g_res[((size_t)fr * NPTS + n) * CDIM + tid] = o * 0.25f;  // mean over heads
    }
}

// ---------------- final: weighted sum over frames + concat ----------------
__global__ __launch_bounds__(128) void final_kernel(const float* __restrict__ seq,
                                                    float* __restrict__ out) {
    const int n = blockIdx.x, c = threadIdx.x;
    const int b = n >> 12;
    float w = 0.f;
#pragma unroll
    for (int i = 0; i < 4; i++)
        w += g_attn[b * 4 + i] * g_res[((size_t)i * NPTS + n) * CDIM + c];
    const float* last = seq + (size_t)4 * NPTS * CDIM;
    out[(size_t)n * 256 + c]       = last[(size_t)n * CDIM + c];
    out[(size_t)n * 256 + 128 + c] = w;
}

// ---------------- launch ----------------
extern "C" void kernel_launch(void* const* d_in, const int* in_sizes, int n_in,
                              void* d_out, int out_size) {
    (void)in_sizes; (void)n_in; (void)out_size;
    const float* seq  = (const float*)d_in[0];
    const float* W1   = (const float*)d_in[1];
    const float* b1   = (const float*)d_in[2];
    const float* W2   = (const float*)d_in[3];
    const float* b2   = (const float*)d_in[4];
    const float* Wl   = (const float*)d_in[5];
    const float* Wr   = (const float*)d_in[6];
    const float* attw = (const float*)d_in[7];
    float* out = (float*)d_out;

    float *pH1, *pXLR;
    cudaGetSymbolAddress((void**)&pH1, g_H1);
    cudaGetSymbolAddress((void**)&pXLR, g_XLR);

    zero_gf_kernel<<<80, 256>>>();

    // H1 = leaky(seq @ W1 + b1)   [81920 x 128]
    gemm_k128<<<dim3(81920 / 64, 128 / 64), 256>>>(seq, W1, b1, pH1, 128, 1);

    // global_fea = mean_m leaky(H1 @ W2 + b2)
    gemm2_reduce_kernel<<<dim3(81920 / 64, GDIM / 64), 256>>>(pH1, W2, b2);

    attn_kernel<<<1, 512>>>();

    // XLR[z] = (z<4 ? past_z @ Wr : last @ Wl)   [16384 x 512] each
    for (int z = 0; z < 5; z++)
        gemm_k128<<<dim3(NPTS / 64, 512 / 64), 256>>>(
            seq + (size_t)z * NPTS * CDIM, (z == 4) ? Wl : Wr, nullptr,
            pXLR + (size_t)z * NPTS * 512, 512, 0);

    // KNN per (frame, batch): fused distance GEMM + top-16
    const int knn_smem = KNN_SMEM_FLOATS * 4;
    cudaFuncSetAttribute(knn_kernel, cudaFuncAttributeMaxDynamicSharedMemorySize, knn_smem);
    knn_kernel<<<dim3(MP / 32, BATCH, 4), 256, knn_smem>>>(seq);

    // GATv2 per (query, frame)
    gat_kernel<<<dim3(NPTS, 4), 128>>>(attw);

    final_kernel<<<NPTS, 128>>>(seq, out);
}

// round 2
// speedup vs baseline: 1.0015x; 1.0015x over previous
#include <cuda_runtime.h>
#include <math.h>

// Problem constants (T=5, B=4, M=4096, C=128, G=1024, H=4, K=16)
#define T_FR   5
#define NPTS   16384
#define CDIM   128
#define GDIM   1024
#define HHEADS 4
#define BATCH  4
#define MP     4096
#define KNB    16

// ---------------- scratch (static __device__ — no allocations) ----------------
__device__ float g_H1[81920 * 128];          // leaky(seq@W1+b1)      ~42 MB
__device__ float g_XLR[5 * 16384 * 512];     // [0..3]=past@Wr, [4]=last@Wl  ~168 MB
__device__ float g_gf[5 * 4 * 1024];         // global_fea means
__device__ float g_attn[16];                 // attn[b][t]
__device__ int   g_nbr[4 * 16384 * 16];      // knn indices (global row ids)
__device__ float g_res[4 * 16384 * 128];     // per-frame GAT outputs ~34 MB

// ---------------- small init ----------------
__global__ void zero_gf_kernel() {
    int i = blockIdx.x * 256 + threadIdx.x;
    if (i < 5 * 4 * 1024) g_gf[i] = 0.f;
}

// ---------------- generic fp32 GEMM, K=128, 64x64 tile, 4x4 micro ----------------
__global__ __launch_bounds__(256) void gemm_k128(
    const float* __restrict__ A, const float* __restrict__ B,
    const float* __restrict__ bias, float* __restrict__ C,
    int Ncols, int leaky)
{
    __shared__ float As[64][68];   // [k][row], padded (68*4B = 272B, 16B-aligned rows)
    __shared__ float Bs[64][68];   // [k][col]
    const int tid = threadIdx.x;
    const int tx = tid & 15, ty = tid >> 4;
    const size_t row0 = (size_t)blockIdx.x * 64;
    const int col0 = blockIdx.y * 64;

    float acc[4][4];
#pragma unroll
    for (int a = 0; a < 4; a++)
#pragma unroll
        for (int bb = 0; bb < 4; bb++) acc[a][bb] = 0.f;

    for (int kc = 0; kc < 2; kc++) {
        const int ks = kc * 64;
#pragma unroll
        for (int it = 0; it < 4; it++) {          // A tile 64 rows x 64 k (transposed store)
            int idx = tid + it * 256;
            int rr = idx >> 4; int kq = (idx & 15) * 4;
            float4 v = *(const float4*)(A + (row0 + rr) * 128 + ks + kq);
            As[kq + 0][rr] = v.x; As[kq + 1][rr] = v.y;
            As[kq + 2][rr] = v.z; As[kq + 3][rr] = v.w;
        }
#pragma unroll
        for (int it = 0; it < 4; it++) {          // B tile 64 k x 64 cols
            int idx = tid + it * 256;
            int kk = idx >> 4; int c4 = (idx & 15) * 4;
            *(float4*)&Bs[kk][c4] = *(const float4*)(B + (size_t)(ks + kk) * Ncols + col0 + c4);
        }
        __syncthreads();
#pragma unroll 16
        for (int k = 0; k < 64; k++) {
            float av[4], bv[4];
#pragma unroll
            for (int j = 0; j < 4; j++) av[j] = As[k][ty + 16 * j];
#pragma unroll
            for (int j = 0; j < 4; j++) bv[j] = Bs[k][tx + 16 * j];
#pragma unroll
            for (int a = 0; a < 4; a++)
#pragma unroll
                for (int bb = 0; bb < 4; bb++) acc[a][bb] += av[a] * bv[bb];
        }
        __syncthreads();
    }
#pragma unroll
    for (int a = 0; a < 4; a++) {
        int r = ty + 16 * a;
#pragma unroll
        for (int bb = 0; bb < 4; bb++) {
            int c = tx + 16 * bb;
            float v = acc[a][bb];
            if (bias) v += bias[col0 + c];
            if (leaky && v < 0.f) v *= 0.2f;
            C[(row0 + r) * Ncols + col0 + c] = v;
        }
    }
}

// ---------------- GEMM2 fused with leaky + column-mean reduce into g_gf ----------------
__global__ __launch_bounds__(256) void gemm2_reduce_kernel(
    const float* __restrict__ A, const float* __restrict__ B,
    const float* __restrict__ bias)
{
    __shared__ float As[64][68];
    __shared__ float Bs[64][68];
    __shared__ float sred[64];
    const int Ncols = GDIM;
    const int tid = threadIdx.x;
    const int tx = tid & 15, ty = tid >> 4;
    const size_t row0 = (size_t)blockIdx.x * 64;
    const int col0 = blockIdx.y * 64;

    float acc[4][4];
#pragma unroll
    for (int a = 0; a < 4; a++)
#pragma unroll
        for (int bb = 0; bb < 4; bb++) acc[a][bb] = 0.f;

    for (int kc = 0; kc < 2; kc++) {
        const int ks = kc * 64;
#pragma unroll
        for (int it = 0; it < 4; it++) {
            int idx = tid + it * 256;
            int rr = idx >> 4; int kq = (idx & 15) * 4;
            float4 v = *(const float4*)(A + (row0 + rr) * 128 + ks + kq);
            As[kq + 0][rr] = v.x; As[kq + 1][rr] = v.y;
            As[kq + 2][rr] = v.z; As[kq + 3][rr] = v.w;
        }
#pragma unroll
        for (int it = 0; it < 4; it++) {
            int idx = tid + it * 256;
            int kk = idx >> 4; int c4 = (idx & 15) * 4;
            *(float4*)&Bs[kk][c4] = *(const float4*)(B + (size_t)(ks + kk) * Ncols + col0 + c4);
        }
        __syncthreads();
#pragma unroll 16
        for (int k = 0; k < 64; k++) {
            float av[4], bv[4];
#pragma unroll
            for (int j = 0; j < 4; j++) av[j] = As[k][ty + 16 * j];
#pragma unroll
            for (int j = 0; j < 4; j++) bv[j] = Bs[k][tx + 16 * j];
#pragma unroll
            for (int a = 0; a < 4; a++)
#pragma unroll
                for (int bb = 0; bb < 4; bb++) acc[a][bb] += av[a] * bv[bb];
        }
        __syncthreads();
    }
    if (tid < 64) sred[tid] = 0.f;
    __syncthreads();
#pragma unroll
    for (int bb = 0; bb < 4; bb++) {
        int c = tx + 16 * bb;
        float bv = bias[col0 + c];
        float s = 0.f;
#pragma unroll
        for (int a = 0; a < 4; a++) {
            float v = acc[a][bb] + bv;
            if (v < 0.f) v *= 0.2f;
            s += v;
        }
        atomicAdd(&sred[c], s);
    }
    __syncthreads();
    if (tid < 64) {
        int t = (int)(row0 >> 14);          // 16384 rows per frame
        int b = (int)((row0 >> 12) & 3);    // 4096 rows per batch
        atomicAdd(&g_gf[(t * 4 + b) * GDIM + col0 + tid], sred[tid] * (1.f / (float)MP));
    }
}

// ---------------- temporal attention weights (tiny) ----------------
__global__ void attn_kernel() {
    __shared__ float sc[16];
    const int tid = threadIdx.x;            // 512
    const int w = tid >> 5, lane = tid & 31;
    const int b = w >> 2, t = w & 3;
    float acc = 0.f;
    for (int g = lane; g < GDIM; g += 32)
        acc += g_gf[(4 * 4 + b) * GDIM + g] * g_gf[(t * 4 + b) * GDIM + g];
#pragma unroll
    for (int o = 16; o; o >>= 1) acc += __shfl_xor_sync(0xffffffffu, acc, o);
    if (lane == 0) sc[b * 4 + t] = acc * (1.f / 32.f);   // /sqrt(1024)
    __syncthreads();
    if (tid < 4) {
        int bb = tid;
        float m = sc[bb * 4];
        for (int i = 1; i < 4; i++) m = fmaxf(m, sc[bb * 4 + i]);
        float e[4], s = 0.f;
        for (int i = 0; i < 4; i++) { e[i] = expf(sc[bb * 4 + i] - m); s += e[i]; }
        for (int i = 0; i < 4; i++) g_attn[bb * 4 + i] = e[i] / s;
    }
}

// ---------------- fused KNN: distance GEMM tile + top-16 selection ----------------
// block = (query-tile of 32, batch, frame). Never materializes D.
#define KNN_SMEM_FLOATS (128*33 + 128*132 + 32*132 + 128 + 32*17 + 32*17)
__global__ __launch_bounds__(256) void knn_kernel(const float* __restrict__ seq) {
    extern __shared__ float sm[];
    float* Ys   = sm;                      // [k][q]  128*33
    float* Xs   = Ys + 128 * 33;           // [k][c]  128*132
    float* Sm   = Xs + 128 * 132;          // [q][c]  32*132
    float* xn   = Sm + 32 * 132;           // 128
    float* topd = xn + 128;                // 32*17 (padded stride 17)
    int*   topi = (int*)(topd + 32 * 17);  // 32*17

    const int tid = threadIdx.x;
    const int qt = blockIdx.x, b = blockIdx.y, fr = blockIdx.z;
    const float* Yb = seq + (size_t)4 * NPTS * CDIM + (size_t)(b * MP + qt * 32) * CDIM;
    const float* Xb = seq + (size_t)fr * NPTS * CDIM + (size_t)b * MP * CDIM;

#pragma unroll
    for (int it = 0; it < 4; it++) {       // Y tile 32 x 128 (transposed)
        int idx = tid + it * 256;
        int q = idx >> 5; int kq = (idx & 31) * 4;
        float4 v = *(const float4*)(Yb + (size_t)q * CDIM + kq);
        Ys[(kq + 0) * 33 + q] = v.x; Ys[(kq + 1) * 33 + q] = v.y;
        Ys[(kq + 2) * 33 + q] = v.z; Ys[(kq + 3) * 33 + q] = v.w;
    }
    for (int e = tid; e < 32 * 16; e += 256) {
        int q = e >> 4, j = e & 15;
        topd[q * 17 + j] = 3.0e38f;
        topi[q * 17 + j] = 0;
    }
    const int tx = tid & 31, ty = tid >> 5;

    for (int cc = 0; cc < MP / 128; cc++) {
        __syncthreads();                   // protect Xs/Sm reuse
#pragma unroll
        for (int it = 0; it < 16; it++) {  // X chunk 128 x 128 (transposed)
            int idx = tid + it * 256;
            int c = idx >> 5; int kq = (idx & 31) * 4;
            float4 v = *(const float4*)(Xb + (size_t)(cc * 128 + c) * CDIM + kq);
            Xs[(kq + 0) * 132 + c] = v.x; Xs[(kq + 1) * 132 + c] = v.y;
            Xs[(kq + 2) * 132 + c] = v.z; Xs[(kq + 3) * 132 + c] = v.w;
        }
        __syncthreads();
        if (tid < 128) {                   // candidate norms
            float s = 0.f;
#pragma unroll 8
            for (int k = 0; k < 128; k++) { float x = Xs[k * 132 + tid]; s += x * x; }
            xn[tid] = s;
        }
        __syncthreads();
        float acc[4][4];
#pragma unroll
        for (int a = 0; a < 4; a++)
#pragma unroll
            for (int bb = 0; bb < 4; bb++) acc[a][bb] = 0.f;
#pragma unroll 8
        for (int k = 0; k < 128; k++) {
            float ya[4], xa[4];
#pragma unroll
            for (int j = 0; j < 4; j++) ya[j] = Ys[k * 33 + ty + 8 * j];
#pragma unroll
            for (int j = 0; j < 4; j++) xa[j] = Xs[k * 132 + tx + 32 * j];
#pragma unroll
            for (int a = 0; a < 4; a++)
#pragma unroll
                for (int bb = 0; bb < 4; bb++) acc[a][bb] += ya[a] * xa[bb];
        }
#pragma unroll
        for (int a = 0; a < 4; a++) {
            int q = ty + 8 * a;
#pragma unroll
            for (int bb = 0; bb < 4; bb++) {
                int c = tx + 32 * bb;
                Sm[q * 132 + c] = xn[c] - 2.f * acc[a][bb];   // |x|^2 - 2 y.x (d minus |y|^2)
            }
        }
        __syncthreads();
        if (tid < 32) {                    // per-query top-16 insertion (tie-stable)
            const int q = tid;
            float* td = topd + q * 17;
            int*   ti = topi + q * 17;
            float worst = td[15];
            for (int c = 0; c < 128; c++) {
                float s = Sm[q * 132 + c];
                if (s < worst) {
                    int j = 15;
                    while (j > 0 && td[j - 1] > s) { td[j] = td[j - 1]; ti[j] = ti[j - 1]; j--; }
                    td[j] = s; ti[j] = cc * 128 + c;
                    worst = td[15];
                }
            }
        }
    }
    __syncthreads();
    for (int e = tid; e < 32 * 16; e += 256) {
        int q = e >> 4, j = e & 15;
        int nglob = b * MP + qt * 32 + q;
        g_nbr[((size_t)fr * NPTS + nglob) * KNB + j] = b * MP + topi[q * 17 + j];
    }
}

// ---------------- GATv2 per (query, frame) ----------------
__global__ __launch_bounds__(128) void gat_kernel(const float* __restrict__ att_w) {
    __shared__ float xls[16 * 512];   // gathered lin_l(last) rows
    __shared__ float xrs[512];
    __shared__ float aws[512];
    __shared__ float es[64];
    __shared__ float as_[64];
    __shared__ int   nb[16];

    const int tid = threadIdx.x;      // 128
    const int n = blockIdx.x, fr = blockIdx.y;
    const float* XL = g_XLR + (size_t)4 * NPTS * 512;
    const float* XR = g_XLR + (size_t)fr * NPTS * 512;

    *(float4*)&xrs[tid * 4] = *(const float4*)(XR + (size_t)n * 512 + tid * 4);
    *(float4*)&aws[tid * 4] = *(const float4*)(att_w + tid * 4);
    if (tid < 16) nb[tid] = g_nbr[((size_t)fr * NPTS + n) * KNB + tid];
    __syncthreads();
#pragma unroll
    for (int k = 0; k < 16; k++)
        *(float4*)&xls[k * 512 + tid * 4] = *(const float4*)(XL + (size_t)nb[k] * 512 + tid * 4);
    __syncthreads();

    if (tid < 64) {                   // e[k][h] = att_w[h] . leaky(xlj + xr)
        const int k = tid & 15, h = tid >> 4;
        float acc = 0.f;
#pragma unroll 4
        for (int cc = 0; cc < 128; cc++) {
            int c = (tid + cc) & 127; // stagger -> conflict-free
            float v = xls[k * 512 + h * 128 + c] + xrs[h * 128 + c];
            v = (v < 0.f) ? 0.2f * v : v;
            acc += aws[h * 128 + c] * v;
        }
        es[h * 16 + k] = acc;
    }
    __syncthreads();
    if (tid < 4) {                    // softmax over k per head
        const int h = tid;
        float m = -1e30f;
        for (int k = 0; k < 16; k++) m = fmaxf(m, es[h * 16 + k]);
        float ex[16], s = 0.f;
        for (int k = 0; k < 16; k++) { ex[k] = expf(es[h * 16 + k] - m); s += ex[k]; }
        float inv = 1.f / s;
        for (int k = 0; k < 16; k++) as_[h * 16 + k] = ex[k] * inv;
    }
    __syncthreads();
    {
        float o = 0.f;
#pragma unroll
        for (int h = 0; h < 4; h++) {
            float oh = 0.f;
#pragma unroll
            for (int k = 0; k < 16; k++)
                oh += as_[h * 16 + k] * xls[k * 512 + h * 128 + tid];
            o += oh;
        }
        g_res[((size_t)fr * NPTS + n) * CDIM + tid] = o * 0.25f;  // mean over heads
    }
}

// ---------------- final: weighted sum over frames + concat ----------------
__global__ __launch_bounds__(128) void final_kernel(const float* __restrict__ seq,
                                                    float* __restrict__ out) {
    const int n = blockIdx.x, c = threadIdx.x;
    const int b = n >> 12;
    float w = 0.f;
#pragma unroll
    for (int i = 0; i < 4; i++)
        w += g_attn[b * 4 + i] * g_res[((size_t)i * NPTS + n) * CDIM + c];
    const float* last = seq + (size_t)4 * NPTS * CDIM;
    out[(size_t)n * 256 + c]       = last[(size_t)n * CDIM + c];
    out[(size_t)n * 256 + 128 + c] = w;
}

// ---------------- launch ----------------
extern "C" void kernel_launch(void* const* d_in, const int* in_sizes, int n_in,
                              void* d_out, int out_size) {
    (void)in_sizes; (void)n_in; (void)out_size;
    const float* seq  = (const float*)d_in[0];
    const float* W1   = (const float*)d_in[1];
    const float* b1   = (const float*)d_in[2];
    const float* W2   = (const float*)d_in[3];
    const float* b2   = (const float*)d_in[4];
    const float* Wl   = (const float*)d_in[5];
    const float* Wr   = (const float*)d_in[6];
    const float* attw = (const float*)d_in[7];
    float* out = (float*)d_out;

    float *pH1, *pXLR;
    cudaGetSymbolAddress((void**)&pH1, g_H1);
    cudaGetSymbolAddress((void**)&pXLR, g_XLR);

    zero_gf_kernel<<<80, 256>>>();

    // H1 = leaky(seq @ W1 + b1)   [81920 x 128]
    gemm_k128<<<dim3(81920 / 64, 128 / 64), 256>>>(seq, W1, b1, pH1, 128, 1);

    // global_fea = mean_m leaky(H1 @ W2 + b2)
    gemm2_reduce_kernel<<<dim3(81920 / 64, GDIM / 64), 256>>>(pH1, W2, b2);

    attn_kernel<<<1, 512>>>();

    // XLR[z] = (z<4 ? past_z @ Wr : last @ Wl)   [16384 x 512] each
    for (int z = 0; z < 5; z++)
        gemm_k128<<<dim3(NPTS / 64, 512 / 64), 256>>>(
            seq + (size_t)z * NPTS * CDIM, (z == 4) ? Wl : Wr, nullptr,
            pXLR + (size_t)z * NPTS * 512, 512, 0);

    // KNN per (frame, batch): fused distance GEMM + top-16
    const int knn_smem = KNN_SMEM_FLOATS * 4;
    cudaFuncSetAttribute(knn_kernel, cudaFuncAttributeMaxDynamicSharedMemorySize, knn_smem);
    knn_kernel<<<dim3(MP / 32, BATCH, 4), 256, knn_smem>>>(seq);

    // GATv2 per (query, frame)
    gat_kernel<<<dim3(NPTS, 4), 128>>>(attw);

    final_kernel<<<NPTS, 128>>>(seq, out);
}